// round 5
// baseline (speedup 1.0000x reference)
#include <cuda_runtime.h>
#include <math.h>
#include <stdint.h>

#define MAX_E 3200000
#define MAX_N 100000
#define FIN 128
#define H1D 64
#define H2D 32
#define NCLS 10
#define SCAN_B 512
#define MAX_BLKS ((MAX_N + SCAN_B) / SCAN_B + 1)

// ---------------- scratch (device globals; referenced directly, no host APIs)
__device__ __align__(16) int   g_indeg[MAX_N];
__device__ __align__(16) int   g_off[MAX_N + 1];
__device__ __align__(16) int   g_pos[MAX_N];
__device__ __align__(16) int   g_part[MAX_N];
__device__ __align__(16) int   g_bsum[MAX_BLKS];
__device__ __align__(16) float g_dinv[MAX_N];
__device__ __align__(16) int   g_esrc[MAX_E];
__device__ __align__(16) float g_enorm[MAX_E];
__device__ __align__(16) float g_h1[MAX_N * H1D];
__device__ __align__(16) float g_a1[MAX_N * H1D];
__device__ __align__(16) float g_h2[MAX_N * H2D];
__device__ __align__(16) float g_a2[MAX_N * H2D];

// compile-time buffer selection per layer width
template <int F> struct Buf;
template <> struct Buf<H1D> {
    static __device__ __forceinline__ float* h() { return g_h1; }
    static __device__ __forceinline__ float* a() { return g_a1; }
};
template <> struct Buf<H2D> {
    static __device__ __forceinline__ float* h() { return g_h2; }
    static __device__ __forceinline__ float* a() { return g_a2; }
};

// ---------------- CSR build ---------------------------------------------------
__global__ void k_zero(int N) {
    int i = blockIdx.x * blockDim.x + threadIdx.x;
    if (i < N) g_indeg[i] = 0;
}

// edge_index is int32 (JAX default x64-disabled): row 0 = src, row 1 = dst
__global__ void k_count(const int* __restrict__ ei, int E) {
    int e = blockIdx.x * blockDim.x + threadIdx.x;
    if (e >= E) return;
    atomicAdd(&g_indeg[ei[e + E]], 1);
}

__global__ void k_scan1(int N) {
    __shared__ int sm[SCAN_B];
    int gid = blockIdx.x * SCAN_B + threadIdx.x;
    int v = (gid < N) ? g_indeg[gid] : 0;
    sm[threadIdx.x] = v;
    __syncthreads();
#pragma unroll
    for (int s = 1; s < SCAN_B; s <<= 1) {
        int t = (threadIdx.x >= (unsigned)s) ? sm[threadIdx.x - s] : 0;
        __syncthreads();
        sm[threadIdx.x] += t;
        __syncthreads();
    }
    if (gid < N) g_part[gid] = sm[threadIdx.x] - v;  // exclusive within block
    if (threadIdx.x == SCAN_B - 1) g_bsum[blockIdx.x] = sm[threadIdx.x];
}

__global__ void k_scan2(int nb) {
    if (threadIdx.x == 0 && blockIdx.x == 0) {
        int running = 0;
        for (int i = 0; i < nb; i++) {
            int t = g_bsum[i];
            g_bsum[i] = running;
            running += t;
        }
    }
}

__global__ void k_scan3(int N, int E) {
    int gid = blockIdx.x * blockDim.x + threadIdx.x;
    if (gid < N) {
        int o = g_part[gid] + g_bsum[gid / SCAN_B];
        g_off[gid] = o;
        g_pos[gid] = o;
    }
    if (gid == 0) g_off[N] = E;
}

__global__ void k_dinv(int N) {
    int i = blockIdx.x * blockDim.x + threadIdx.x;
    if (i < N) g_dinv[i] = rsqrtf((float)g_indeg[i] + 1.0f);
}

__global__ void k_fill(const int* __restrict__ ei, int E) {
    int e = blockIdx.x * blockDim.x + threadIdx.x;
    if (e >= E) return;
    int s = ei[e];
    int d = ei[e + E];
    int p = atomicAdd(&g_pos[d], 1);
    g_esrc[p]  = s;
    g_enorm[p] = g_dinv[s] * g_dinv[d];
}

// ---------------- dense GEMM: out[N,ODIM] = (relu?)X[N,KDIM] @ W[KDIM,ODIM] --
// LAYER 1: X = feat param, out = g_h1. LAYER 2: X = g_a1, out = g_h2.
template <int KDIM, int ODIM, bool RELU_IN, int LAYER>
__global__ void k_gemm(const float* __restrict__ Xparam, const float* __restrict__ Wg,
                       int N) {
    const float* X  = (LAYER == 1) ? Xparam : g_a1;
    float*      out = (LAYER == 1) ? g_h1   : g_h2;

    constexpr int NL  = 256 / ODIM;   // row-lanes
    constexpr int RPT = 4;            // rows per thread
    constexpr int RPB = NL * RPT;     // rows per block
    __shared__ float Wsm[KDIM * ODIM];
    __shared__ float Xsm[RPB * KDIM];

    int tid = threadIdx.x;
    for (int i = tid; i < KDIM * ODIM; i += 256) Wsm[i] = Wg[i];

    int row0 = blockIdx.x * RPB;
    for (int i = tid; i < RPB * KDIM; i += 256) {
        int r = i / KDIM, k = i - r * KDIM;
        int gr = row0 + r;
        float v = (gr < N) ? X[(size_t)gr * KDIM + k] : 0.0f;
        if (RELU_IN) v = fmaxf(v, 0.0f);
        Xsm[i] = v;
    }
    __syncthreads();

    int col = tid % ODIM;
    int rl  = tid / ODIM;
    float acc[RPT];
#pragma unroll
    for (int j = 0; j < RPT; j++) acc[j] = 0.0f;

#pragma unroll 4
    for (int k = 0; k < KDIM; k++) {
        float w = Wsm[k * ODIM + col];
#pragma unroll
        for (int j = 0; j < RPT; j++)
            acc[j] += Xsm[(rl * RPT + j) * KDIM + k] * w;
    }
#pragma unroll
    for (int j = 0; j < RPT; j++) {
        int gr = row0 + rl * RPT + j;
        if (gr < N) out[(size_t)gr * ODIM + col] = acc[j];
    }
}

// -------- CSR gather: a[i] = sum_j h[src_j]*norm_j + h[i]*dinv[i]^2 + b ------
template <int F>
__global__ void k_gather(const float* __restrict__ b, int N) {
    const float* h  = Buf<F>::h();
    float*      out = Buf<F>::a();

    int node = blockIdx.x * (blockDim.x >> 5) + (threadIdx.x >> 5);
    int lane = threadIdx.x & 31;
    if (node >= N) return;

    int beg = g_off[node];
    int end = g_off[node + 1];

    constexpr int C = F / 32;
    float acc[C];
#pragma unroll
    for (int c = 0; c < C; c++) acc[c] = 0.0f;

    int j = beg;
    for (; j + 1 < end; j += 2) {          // 2-edge pipeline for MLP
        int   s0 = __ldg(&g_esrc[j]);
        int   s1 = __ldg(&g_esrc[j + 1]);
        float n0 = __ldg(&g_enorm[j]);
        float n1 = __ldg(&g_enorm[j + 1]);
        const float* r0 = h + (size_t)s0 * F;
        const float* r1 = h + (size_t)s1 * F;
#pragma unroll
        for (int c = 0; c < C; c++) {
            acc[c] += __ldg(&r0[lane + 32 * c]) * n0;
            acc[c] += __ldg(&r1[lane + 32 * c]) * n1;
        }
    }
    if (j < end) {
        int   s0 = __ldg(&g_esrc[j]);
        float n0 = __ldg(&g_enorm[j]);
        const float* r0 = h + (size_t)s0 * F;
#pragma unroll
        for (int c = 0; c < C; c++) acc[c] += __ldg(&r0[lane + 32 * c]) * n0;
    }

    float di = g_dinv[node];
    float d2 = di * di;
    const float* hr = h + (size_t)node * F;
#pragma unroll
    for (int c = 0; c < C; c++) {
        int col = lane + 32 * c;
        out[(size_t)node * F + col] = acc[c] + hr[col] * d2 + b[col];
    }
}

// ---------------- classifier + log_softmax -----------------------------------
__global__ void k_final(const float* __restrict__ Wc, const float* __restrict__ bc,
                        float* __restrict__ out, int N) {
    __shared__ float Wsm[H2D * NCLS];
    __shared__ float bsm[NCLS];
    int tid = threadIdx.x;
    for (int i = tid; i < H2D * NCLS; i += blockDim.x) Wsm[i] = Wc[i];
    if (tid < NCLS) bsm[tid] = bc[tid];
    __syncthreads();

    int i = blockIdx.x * blockDim.x + tid;
    if (i >= N) return;

    float x[H2D];
    const float4* row = (const float4*)(g_a2 + (size_t)i * H2D);
#pragma unroll
    for (int k = 0; k < H2D / 4; k++) {
        float4 v = row[k];
        x[4 * k + 0] = fmaxf(v.x, 0.0f);
        x[4 * k + 1] = fmaxf(v.y, 0.0f);
        x[4 * k + 2] = fmaxf(v.z, 0.0f);
        x[4 * k + 3] = fmaxf(v.w, 0.0f);
    }

    float lg[NCLS];
#pragma unroll
    for (int c = 0; c < NCLS; c++) {
        float acc = bsm[c];
#pragma unroll
        for (int k = 0; k < H2D; k++) acc += x[k] * Wsm[k * NCLS + c];
        lg[c] = acc;
    }
    float mx = lg[0];
#pragma unroll
    for (int c = 1; c < NCLS; c++) mx = fmaxf(mx, lg[c]);
    float sum = 0.0f;
#pragma unroll
    for (int c = 0; c < NCLS; c++) sum += __expf(lg[c] - mx);
    float lse = mx + logf(sum);
#pragma unroll
    for (int c = 0; c < NCLS; c++) out[(size_t)i * NCLS + c] = lg[c] - lse;
}

// ---------------- launch (kernel launches ONLY; graph-capture clean) ---------
extern "C" void kernel_launch(void* const* d_in, const int* in_sizes, int n_in,
                              void* d_out, int out_size) {
    const float* feat = (const float*)d_in[0];
    const int*   ei   = (const int*)d_in[1];    // int32! (JAX x64 disabled)
    const float* W1   = (const float*)d_in[2];
    const float* b1   = (const float*)d_in[3];
    const float* W2   = (const float*)d_in[4];
    const float* b2   = (const float*)d_in[5];
    const float* Wc   = (const float*)d_in[6];
    const float* bc   = (const float*)d_in[7];

    int N = in_sizes[0] / FIN;
    int E = in_sizes[1] / 2;

    const int T = 256;
    int nb = (N + SCAN_B - 1) / SCAN_B;

    // CSR build
    k_zero<<<(N + T - 1) / T, T>>>(N);
    k_count<<<(E + T - 1) / T, T>>>(ei, E);
    k_scan1<<<nb, SCAN_B>>>(N);
    k_scan2<<<1, 32>>>(nb);
    k_scan3<<<(N + T - 1) / T, T>>>(N, E);
    k_dinv<<<(N + T - 1) / T, T>>>(N);
    k_fill<<<(E + T - 1) / T, T>>>(ei, E);

    // layer 1
    k_gemm<FIN, H1D, false, 1><<<(N + 15) / 16, 256>>>(feat, W1, N);
    k_gather<H1D><<<(N + 7) / 8, 256>>>(b1, N);

    // layer 2
    k_gemm<H1D, H2D, true, 2><<<(N + 31) / 32, 256>>>(nullptr, W2, N);
    k_gather<H2D><<<(N + 7) / 8, 256>>>(b2, N);

    // classifier + log_softmax
    k_final<<<(N + 127) / 128, 128>>>(Wc, bc, (float*)d_out, N);
}